// round 4
// baseline (speedup 1.0000x reference)
#include <cuda_runtime.h>
#include <cuda_bf16.h>
#include <stdint.h>

#define BB 4
#define NN 2048
#define MM 2048
#define DD 1024
#define HH 16
#define DKK 64
#define RR (BB*NN)
#define NEGV -1e32f

#define EL_X ((size_t)RR*DD)     // 8,388,608
#define EL_W ((size_t)DD*DD)     // 1,048,576

// bf16 arena: 12 X-sized slots + 8 weight slots
__device__ __nv_bfloat16 g_bf[12*EL_X + 8*EL_W];
__device__ float g_beta_scratch[(size_t)BB*HH*NN*MM];
__device__ float g_rowsum[(size_t)BB*HH*NN];

// ---------------------------------------------------------------------------
__device__ __forceinline__ uint32_t smem_u32(const void* p) {
    uint32_t a;
    asm("{ .reg .u64 t; cvta.to.shared.u64 t, %1; cvt.u32.u64 %0, t; }"
        : "=r"(a) : "l"(p));
    return a;
}

#define CP16(s, g) \
    asm volatile("cp.async.cg.shared.global [%0], [%1], 16;" :: "r"(s), "l"(g))
#define CPC() asm volatile("cp.async.commit_group;" ::: "memory")
#define CPW(n) asm volatile("cp.async.wait_group %0;" :: "n"(n) : "memory")

#define LDSM4(r, addr) \
    asm volatile("ldmatrix.sync.aligned.m8n8.x4.shared.b16 {%0,%1,%2,%3}, [%4];" \
        : "=r"((r)[0]), "=r"((r)[1]), "=r"((r)[2]), "=r"((r)[3]) : "r"(addr))
#define LDSM4T(r, addr) \
    asm volatile("ldmatrix.sync.aligned.m8n8.x4.trans.shared.b16 {%0,%1,%2,%3}, [%4];" \
        : "=r"((r)[0]), "=r"((r)[1]), "=r"((r)[2]), "=r"((r)[3]) : "r"(addr))

#define MMA_BF16(d, a, b0, b1) \
    asm volatile("mma.sync.aligned.m16n8k16.row.col.f32.bf16.bf16.f32 " \
        "{%0,%1,%2,%3}, {%4,%5,%6,%7}, {%8,%9}, {%0,%1,%2,%3};" \
        : "+f"((d)[0]), "+f"((d)[1]), "+f"((d)[2]), "+f"((d)[3]) \
        : "r"((a)[0]), "r"((a)[1]), "r"((a)[2]), "r"((a)[3]), "r"(b0), "r"(b1))

__device__ __forceinline__ uint32_t pack_hi(float x, float y) {
    __nv_bfloat162 v(__float2bfloat16(x), __float2bfloat16(y));
    return *(uint32_t*)&v;
}
__device__ __forceinline__ uint32_t pack_lo(float x, float y) {
    float hx = __bfloat162float(__float2bfloat16(x));
    float hy = __bfloat162float(__float2bfloat16(y));
    __nv_bfloat162 v(__float2bfloat16(x - hx), __float2bfloat16(y - hy));
    return *(uint32_t*)&v;
}

// ---------------------------------------------------------------------------
// fp32 -> bf16 hi/lo split
// ---------------------------------------------------------------------------
__global__ void __launch_bounds__(256) conv_split(const float* __restrict__ src,
                                                  __nv_bfloat16* __restrict__ hi,
                                                  __nv_bfloat16* __restrict__ lo,
                                                  int n4)
{
    int i = blockIdx.x * blockDim.x + threadIdx.x;
    if (i >= n4) return;
    float4 v = ((const float4*)src)[i];
    uint32_t* hp = (uint32_t*)hi;
    uint32_t* lp = (uint32_t*)lo;
    hp[2*i]   = pack_hi(v.x, v.y);
    hp[2*i+1] = pack_hi(v.z, v.w);
    lp[2*i]   = pack_lo(v.x, v.y);
    lp[2*i+1] = pack_lo(v.z, v.w);
}

// ---------------------------------------------------------------------------
// Projection GEMM: C[r,c] = sum_k A[r,k]*W[c,k] + bias[c], split-bf16 3-term.
// 128x128 CTA tile, BK=64, 48 k-tiles (3 phases x 16), cp.async double buffer.
// ---------------------------------------------------------------------------
template<int OUTMODE>
__global__ void __launch_bounds__(256,2) gemm_proj(
    const __nv_bfloat16* __restrict__ Ah, const __nv_bfloat16* __restrict__ Al,
    const __nv_bfloat16* __restrict__ Wh, const __nv_bfloat16* __restrict__ Wl,
    const float* __restrict__ bias,
    float* __restrict__ outF,
    __nv_bfloat16* __restrict__ outH, __nv_bfloat16* __restrict__ outL)
{
    extern __shared__ __nv_bfloat16 sm[];
    const int tid  = threadIdx.x;
    const int lane = tid & 31;
    const int wid  = tid >> 5;
    const int wm   = wid & 3;
    const int wn   = wid >> 2;
    const int row0 = blockIdx.y * 128;
    const int col0 = blockIdx.x * 128;
    const uint32_t sbase = smem_u32(sm);

    float acc[2][8][4];
    #pragma unroll
    for (int i = 0; i < 2; i++)
        #pragma unroll
        for (int j = 0; j < 8; j++)
            #pragma unroll
            for (int q = 0; q < 4; q++) acc[i][j][q] = 0.f;

    #define ISSUE(t) do {                                                      \
        const int p  = (t) >> 4;                                               \
        const int k0 = ((t) & 15) << 6;                                        \
        const __nv_bfloat16* Ap = (p == 1) ? Al : Ah;                          \
        const __nv_bfloat16* Wp = (p == 2) ? Wl : Wh;                          \
        const uint32_t sA = sbase + ((t & 1) * 9216) * 2;                      \
        const uint32_t sW = sbase + (18432 + (t & 1) * 9216) * 2;              \
        _Pragma("unroll")                                                      \
        for (int i_ = 0; i_ < 4; i_++) {                                       \
            int idx = tid + i_ * 256;                                          \
            int r = idx >> 3, ch = idx & 7;                                    \
            CP16(sA + (r * 72 + ch * 8) * 2,                                   \
                 Ap + (size_t)(row0 + r) * DD + k0 + ch * 8);                  \
            CP16(sW + (r * 72 + ch * 8) * 2,                                   \
                 Wp + (size_t)(col0 + r) * DD + k0 + ch * 8);                  \
        }                                                                      \
        CPC();                                                                 \
    } while (0)

    ISSUE(0);
    for (int t = 0; t < 48; t++) {
        if (t + 1 < 48) { ISSUE(t + 1); CPW(1); }
        else            { CPW(0); }
        __syncthreads();
        const uint32_t sA = sbase + ((t & 1) * 9216) * 2;
        const uint32_t sW = sbase + (18432 + (t & 1) * 9216) * 2;
        #pragma unroll
        for (int ks = 0; ks < 4; ks++) {
            uint32_t a[2][4], bq[4][4];
            #pragma unroll
            for (int i = 0; i < 2; i++)
                LDSM4(a[i], sA + ((wm*32 + i*16 + (lane & 15)) * 72
                                  + ks*16 + (lane >> 4) * 8) * 2);
            #pragma unroll
            for (int jj = 0; jj < 4; jj++)
                LDSM4(bq[jj], sW + ((wn*64 + jj*16 + (lane & 15)) * 72
                                    + ks*16 + (lane >> 4) * 8) * 2);
            #pragma unroll
            for (int i = 0; i < 2; i++)
                #pragma unroll
                for (int j = 0; j < 8; j++) {
                    const int jj = j >> 1;
                    uint32_t b0 = (j & 1) ? bq[jj][1] : bq[jj][0];
                    uint32_t b1 = (j & 1) ? bq[jj][3] : bq[jj][2];
                    MMA_BF16(acc[i][j], a[i], b0, b1);
                }
        }
        __syncthreads();
    }
    #undef ISSUE

    const int bb = row0 >> 11;
    #pragma unroll
    for (int i = 0; i < 2; i++) {
        const int r  = row0 + wm*32 + i*16 + (lane >> 2);
        const int n  = r & 2047;
        #pragma unroll
        for (int j = 0; j < 8; j++) {
            const int c = col0 + wn*64 + j*8 + (lane & 3)*2;
            const float b0v = __ldg(bias + c), b1v = __ldg(bias + c + 1);
            const float v00 = acc[i][j][0] + b0v, v01 = acc[i][j][1] + b1v;
            const float v10 = acc[i][j][2] + b0v, v11 = acc[i][j][3] + b1v;
            if (OUTMODE == 0) {
                *(float2*)(outF + (size_t)r * DD + c)       = make_float2(v00, v01);
                *(float2*)(outF + (size_t)(r + 8) * DD + c) = make_float2(v10, v11);
            } else {
                const int h = c >> 6, dk = c & 63;
                const size_t a0 = ((((size_t)bb*HH + h)*NN + n)      << 6) + dk;
                const size_t a1 = ((((size_t)bb*HH + h)*NN + (n+8))  << 6) + dk;
                *(uint32_t*)(outH + a0) = pack_hi(v00, v01);
                *(uint32_t*)(outL + a0) = pack_lo(v00, v01);
                *(uint32_t*)(outH + a1) = pack_hi(v10, v11);
                *(uint32_t*)(outL + a1) = pack_lo(v10, v11);
            }
        }
    }
}

// ---------------------------------------------------------------------------
// Scores + exp fused: writes UNNORMALIZED exp(scale*QK) (masked -> 0) to beta,
// accumulates per-row sums into g_rowsum (no max subtraction: |logit| < ~3).
// ---------------------------------------------------------------------------
__global__ void __launch_bounds__(256,2) scores_mma(
    const int* __restrict__ mask, float* __restrict__ beta,
    const __nv_bfloat16* __restrict__ QH, const __nv_bfloat16* __restrict__ QL,
    const __nv_bfloat16* __restrict__ KH, const __nv_bfloat16* __restrict__ KL)
{
    extern __shared__ __nv_bfloat16 sm[];
    const int tid  = threadIdx.x;
    const int lane = tid & 31;
    const int wid  = tid >> 5;
    const int wm   = wid & 3;
    const int wn   = wid >> 2;
    const int z    = blockIdx.z;
    const int b    = z >> 4;
    const int m0   = blockIdx.x * 128;
    const int n0   = blockIdx.y * 128;
    const uint32_t sbase = smem_u32(sm);

    const __nv_bfloat16* srcs[4] = {
        QH + ((size_t)z*NN + n0) * DKK, QL + ((size_t)z*NN + n0) * DKK,
        KH + ((size_t)z*MM + m0) * DKK, KL + ((size_t)z*MM + m0) * DKK };

    #pragma unroll
    for (int ts = 0; ts < 4; ts++) {
        #pragma unroll
        for (int i = 0; i < 4; i++) {
            int idx = tid + i * 256;
            int r = idx >> 3, ch = idx & 7;
            CP16(sbase + (ts*9216 + r*72 + ch*8) * 2,
                 srcs[ts] + (size_t)r * DKK + ch * 8);
        }
    }
    CPC(); CPW(0);
    __syncthreads();

    float acc[2][8][4];
    #pragma unroll
    for (int i = 0; i < 2; i++)
        #pragma unroll
        for (int j = 0; j < 8; j++)
            #pragma unroll
            for (int q = 0; q < 4; q++) acc[i][j][q] = 0.f;

    #pragma unroll
    for (int p = 0; p < 3; p++) {
        const uint32_t sA = sbase + ((p == 1) ? 9216 : 0) * 2;
        const uint32_t sB = sbase + ((p == 2) ? 27648 : 18432) * 2;
        #pragma unroll
        for (int ks = 0; ks < 4; ks++) {
            uint32_t a[2][4], bq[4][4];
            #pragma unroll
            for (int i = 0; i < 2; i++)
                LDSM4(a[i], sA + ((wm*32 + i*16 + (lane & 15)) * 72
                                  + ks*16 + (lane >> 4) * 8) * 2);
            #pragma unroll
            for (int jj = 0; jj < 4; jj++)
                LDSM4(bq[jj], sB + ((wn*64 + jj*16 + (lane & 15)) * 72
                                    + ks*16 + (lane >> 4) * 8) * 2);
            #pragma unroll
            for (int i = 0; i < 2; i++)
                #pragma unroll
                for (int j = 0; j < 8; j++) {
                    const int jj = j >> 1;
                    uint32_t b0 = (j & 1) ? bq[jj][1] : bq[jj][0];
                    uint32_t b1 = (j & 1) ? bq[jj][3] : bq[jj][2];
                    MMA_BF16(acc[i][j], a[i], b0, b1);
                }
        }
    }

    const float scl = 0.125f;
    float rsum[4] = {0.f, 0.f, 0.f, 0.f};
    #pragma unroll
    for (int i = 0; i < 2; i++) {
        const int n = n0 + wm*32 + i*16 + (lane >> 2);
        const int* mr0 = mask + ((size_t)b*NN + n) * MM;
        const int* mr1 = mask + ((size_t)b*NN + n + 8) * MM;
        float* br0 = beta + ((size_t)z*NN + n) * MM;
        float* br1 = beta + ((size_t)z*NN + n + 8) * MM;
        #pragma unroll
        for (int j = 0; j < 8; j++) {
            const int c = m0 + wn*64 + j*8 + (lane & 3)*2;
            int2 k0 = *(const int2*)(mr0 + c);
            int2 k1 = *(const int2*)(mr1 + c);
            float2 o0, o1;
            o0.x = (k0.x == 1) ? 0.f : __expf(acc[i][j][0] * scl);
            o0.y = (k0.y == 1) ? 0.f : __expf(acc[i][j][1] * scl);
            o1.x = (k1.x == 1) ? 0.f : __expf(acc[i][j][2] * scl);
            o1.y = (k1.y == 1) ? 0.f : __expf(acc[i][j][3] * scl);
            rsum[i*2+0] += o0.x + o0.y;
            rsum[i*2+1] += o1.x + o1.y;
            *(float2*)(br0 + c) = o0;
            *(float2*)(br1 + c) = o1;
        }
    }

    // reduce over the 4 lanes sharing each row (lane & 3)
    #pragma unroll
    for (int k = 0; k < 4; k++) {
        rsum[k] += __shfl_xor_sync(0xffffffffu, rsum[k], 1);
        rsum[k] += __shfl_xor_sync(0xffffffffu, rsum[k], 2);
    }
    __shared__ float srow[128];
    if (tid < 128) srow[tid] = 0.f;
    __syncthreads();
    if ((lane & 3) == 0) {
        #pragma unroll
        for (int k = 0; k < 4; k++) {
            const int rl = wm*32 + (k >> 1)*16 + (k & 1)*8 + (lane >> 2);
            atomicAdd(&srow[rl], rsum[k]);
        }
    }
    __syncthreads();
    if (tid < 128)
        atomicAdd(&g_rowsum[(size_t)z*NN + n0 + tid], srow[tid]);
}

// ---------------------------------------------------------------------------
// wt = beta_norm @ V per (b,h). Normalizes the streaming exp-beta tile with
// 1/rowsum, writes the normalized value BACK to beta (final output), and
// accumulates the P*V mma on the normalized values (3-term split bf16).
// ---------------------------------------------------------------------------
__global__ void __launch_bounds__(256,2) av_mma(
    float* __restrict__ beta,
    const __nv_bfloat16* __restrict__ VH, const __nv_bfloat16* __restrict__ VL,
    __nv_bfloat16* __restrict__ WtH, __nv_bfloat16* __restrict__ WtL)
{
    extern __shared__ __nv_bfloat16 sm[];
    __shared__ float inv_s[128];
    const int tid  = threadIdx.x;
    const int lane = tid & 31;
    const int wid  = tid >> 5;
    const int z    = blockIdx.y;
    const int b    = z >> 4;
    const int h    = z & 15;
    const int n0   = blockIdx.x * 128;
    const uint32_t sbase = smem_u32(sm);

    float* Bsrc = beta + ((size_t)z*NN + n0) * MM;
    const __nv_bfloat16* Vh_g = VH + (size_t)z * MM * DKK;
    const __nv_bfloat16* Vl_g = VL + (size_t)z * MM * DKK;

    if (tid < 128)
        inv_s[tid] = 1.0f / g_rowsum[(size_t)z*NN + n0 + tid];
    __syncthreads();

    float acc[8][4];
    #pragma unroll
    for (int j = 0; j < 8; j++)
        #pragma unroll
        for (int q = 0; q < 4; q++) acc[j][q] = 0.f;

    for (int k0 = 0; k0 < MM; k0 += 64) {
        #pragma unroll
        for (int i = 0; i < 8; i++) {
            int idx = tid + i * 256;
            int r = idx >> 4, ch = idx & 15;
            float4 v = *(const float4*)(Bsrc + (size_t)r * MM + k0 + ch * 4);
            const float iv = inv_s[r];
            v.x *= iv; v.y *= iv; v.z *= iv; v.w *= iv;
            *(float4*)(Bsrc + (size_t)r * MM + k0 + ch * 4) = v;
            uint32_t* ph = (uint32_t*)(sm + r*72 + ch*4);
            uint32_t* pl = (uint32_t*)(sm + 9216 + r*72 + ch*4);
            ph[0] = pack_hi(v.x, v.y); ph[1] = pack_hi(v.z, v.w);
            pl[0] = pack_lo(v.x, v.y); pl[1] = pack_lo(v.z, v.w);
        }
        #pragma unroll
        for (int i = 0; i < 4; i++) {
            int idx = tid + i * 256;
            int ts = idx >> 9, r = (idx >> 3) & 63, ch = idx & 7;
            const __nv_bfloat16* vs = ts ? Vl_g : Vh_g;
            *(uint4*)(sm + 18432 + ts*4608 + r*72 + ch*8) =
                *(const uint4*)(vs + (size_t)(k0 + r) * DKK + ch * 8);
        }
        __syncthreads();

        #pragma unroll
        for (int p = 0; p < 3; p++) {
            const uint32_t sA = sbase + ((p == 1) ? 9216 : 0) * 2;
            const uint32_t sV = sbase + (18432 + ((p == 2) ? 4608 : 0)) * 2;
            #pragma unroll
            for (int ks = 0; ks < 4; ks++) {
                uint32_t a[4], bq[4][4];
                LDSM4(a, sA + ((wid*16 + (lane & 15)) * 72
                               + ks*16 + (lane >> 4) * 8) * 2);
                #pragma unroll
                for (int jj = 0; jj < 4; jj++)
                    LDSM4T(bq[jj], sV + ((ks*16 + ((lane >> 3) & 1)*8 + (lane & 7)) * 72
                                         + jj*16 + (lane >> 4) * 8) * 2);
                #pragma unroll
                for (int j = 0; j < 8; j++) {
                    const int jj = j >> 1;
                    uint32_t b0 = (j & 1) ? bq[jj][2] : bq[jj][0];
                    uint32_t b1 = (j & 1) ? bq[jj][3] : bq[jj][1];
                    MMA_BF16(acc[j], a, b0, b1);
                }
            }
        }
        __syncthreads();
    }

    const int n = n0 + wid*16 + (lane >> 2);
    #pragma unroll
    for (int j = 0; j < 8; j++) {
        const int dk = j*8 + (lane & 3)*2;
        const size_t a0 = ((((size_t)b*NN + n)    * HH + h) << 6) + dk;
        const size_t a1 = ((((size_t)b*NN + n + 8)* HH + h) << 6) + dk;
        *(uint32_t*)(WtH + a0) = pack_hi(acc[j][0], acc[j][1]);
        *(uint32_t*)(WtL + a0) = pack_lo(acc[j][0], acc[j][1]);
        *(uint32_t*)(WtH + a1) = pack_hi(acc[j][2], acc[j][3]);
        *(uint32_t*)(WtL + a1) = pack_lo(acc[j][2], acc[j][3]);
    }
}

// ============================================================================
extern "C" void kernel_launch(void* const* d_in, const int* in_sizes, int n_in,
                              void* d_out, int out_size)
{
    const float* X    = (const float*)d_in[0];
    const float* Y    = (const float*)d_in[1];
    const int*   mask = (const int*)  d_in[2];
    const float* Wq   = (const float*)d_in[3];
    const float* bq   = (const float*)d_in[4];
    const float* Wk   = (const float*)d_in[5];
    const float* bk   = (const float*)d_in[6];
    const float* Wv   = (const float*)d_in[7];
    const float* bv   = (const float*)d_in[8];
    const float* Wo   = (const float*)d_in[9];
    const float* bo   = (const float*)d_in[10];
    float* out = (float*)d_out;

    const size_t ATTN = (size_t)BB * NN * DD;
    const size_t BETA = (size_t)BB * HH * NN * MM;

    void *bfp_, *bsp_, *rsp_;
    cudaGetSymbolAddress(&bfp_, g_bf);
    cudaGetSymbolAddress(&bsp_, g_beta_scratch);
    cudaGetSymbolAddress(&rsp_, g_rowsum);
    __nv_bfloat16* bf = (__nv_bfloat16*)bfp_;

    __nv_bfloat16* XH = bf + 0*EL_X;  __nv_bfloat16* XL = bf + 1*EL_X;
    __nv_bfloat16* YH = bf + 2*EL_X;  __nv_bfloat16* YL = bf + 3*EL_X;
    __nv_bfloat16* QH = bf + 4*EL_X;  __nv_bfloat16* QL = bf + 5*EL_X;
    __nv_bfloat16* KH = bf + 6*EL_X;  __nv_bfloat16* KL = bf + 7*EL_X;
    __nv_bfloat16* VH = bf + 8*EL_X;  __nv_bfloat16* VL = bf + 9*EL_X;
    __nv_bfloat16* TH = bf + 10*EL_X; __nv_bfloat16* TL = bf + 11*EL_X;
    __nv_bfloat16* W0 = bf + 12*EL_X;
    __nv_bfloat16* WqH = W0 + 0*EL_W; __nv_bfloat16* WqL = W0 + 1*EL_W;
    __nv_bfloat16* WkH = W0 + 2*EL_W; __nv_bfloat16* WkL = W0 + 3*EL_W;
    __nv_bfloat16* WvH = W0 + 4*EL_W; __nv_bfloat16* WvL = W0 + 5*EL_W;
    __nv_bfloat16* WoH = W0 + 6*EL_W; __nv_bfloat16* WoL = W0 + 7*EL_W;

    float* beta = ((size_t)out_size >= ATTN + BETA) ? (out + ATTN)
                                                    : (float*)bsp_;

    const int SMP = 73728;
    const int SMA = 55296;
    cudaFuncSetAttribute(gemm_proj<0>, cudaFuncAttributeMaxDynamicSharedMemorySize, SMP);
    cudaFuncSetAttribute(gemm_proj<1>, cudaFuncAttributeMaxDynamicSharedMemorySize, SMP);
    cudaFuncSetAttribute(scores_mma,   cudaFuncAttributeMaxDynamicSharedMemorySize, SMP);
    cudaFuncSetAttribute(av_mma,       cudaFuncAttributeMaxDynamicSharedMemorySize, SMA);

    const int n4x = (int)(EL_X / 4);
    const int n4w = (int)(EL_W / 4);
    conv_split<<<(n4x + 255)/256, 256>>>(X,  XH, XL, n4x);
    conv_split<<<(n4x + 255)/256, 256>>>(Y,  YH, YL, n4x);
    conv_split<<<(n4w + 255)/256, 256>>>(Wq, WqH, WqL, n4w);
    conv_split<<<(n4w + 255)/256, 256>>>(Wk, WkH, WkL, n4w);
    conv_split<<<(n4w + 255)/256, 256>>>(Wv, WvH, WvL, n4w);
    conv_split<<<(n4w + 255)/256, 256>>>(Wo, WoH, WoL, n4w);

    cudaMemsetAsync(rsp_, 0, (size_t)BB*HH*NN*sizeof(float));

    const dim3 pgrid(DD/128, RR/128);
    gemm_proj<1><<<pgrid, 256, SMP>>>(XH, XL, WqH, WqL, bq, nullptr, QH, QL);
    gemm_proj<1><<<pgrid, 256, SMP>>>(YH, YL, WkH, WkL, bk, nullptr, KH, KL);
    gemm_proj<1><<<pgrid, 256, SMP>>>(YH, YL, WvH, WvL, bv, nullptr, VH, VL);

    scores_mma<<<dim3(MM/128, NN/128, BB*HH), 256, SMP>>>(mask, beta, QH, QL, KH, KL);

    av_mma<<<dim3(NN/128, BB*HH), 256, SMA>>>(beta, VH, VL, TH, TL);

    gemm_proj<0><<<pgrid, 256, SMP>>>(TH, TL, WoH, WoL, bo, out, nullptr, nullptr);
}

// round 6
// speedup vs baseline: 1.2416x; 1.2416x over previous
#include <cuda_runtime.h>
#include <cuda_bf16.h>
#include <cuda_fp16.h>
#include <stdint.h>

#define BB 4
#define NN 2048
#define MM 2048
#define DD 1024
#define HH 16
#define DKK 64
#define RR (BB*NN)

#define EL_X ((size_t)RR*DD)     // 8,388,608
#define EL_W ((size_t)DD*DD)     // 1,048,576

// bf16 arena: slots 0 XH,1 XL,2 YH,3 YL,4 QH,5 QL,6 KH,7 KL,8 VH,9 VL,10 TH,11 TL
__device__ __nv_bfloat16 g_bf[12*EL_X + 8*EL_W];
__device__ __half g_p16[(size_t)BB*HH*NN*MM];          // unnormalized exp scratch
__device__ float g_rowsum[(size_t)BB*HH*NN];
__device__ float g_beta_scratch[(size_t)BB*HH*NN*MM];  // fallback only

extern __shared__ char smraw[];   // single TU-wide dynamic smem symbol

// ---------------------------------------------------------------------------
__device__ __forceinline__ uint32_t smem_u32(const void* p) {
    uint32_t a;
    asm("{ .reg .u64 t; cvta.to.shared.u64 t, %1; cvt.u32.u64 %0, t; }"
        : "=r"(a) : "l"(p));
    return a;
}

#define CP16(s, g) \
    asm volatile("cp.async.cg.shared.global [%0], [%1], 16;" :: "r"(s), "l"(g))
#define CPC() asm volatile("cp.async.commit_group;" ::: "memory")
#define CPW(n) asm volatile("cp.async.wait_group %0;" :: "n"(n) : "memory")

#define LDSM4(r, addr) \
    asm volatile("ldmatrix.sync.aligned.m8n8.x4.shared.b16 {%0,%1,%2,%3}, [%4];" \
        : "=r"((r)[0]), "=r"((r)[1]), "=r"((r)[2]), "=r"((r)[3]) : "r"(addr))
#define LDSM4T(r, addr) \
    asm volatile("ldmatrix.sync.aligned.m8n8.x4.trans.shared.b16 {%0,%1,%2,%3}, [%4];" \
        : "=r"((r)[0]), "=r"((r)[1]), "=r"((r)[2]), "=r"((r)[3]) : "r"(addr))

#define MMA_BF16(d, a, b0, b1) \
    asm volatile("mma.sync.aligned.m16n8k16.row.col.f32.bf16.bf16.f32 " \
        "{%0,%1,%2,%3}, {%4,%5,%6,%7}, {%8,%9}, {%0,%1,%2,%3};" \
        : "+f"((d)[0]), "+f"((d)[1]), "+f"((d)[2]), "+f"((d)[3]) \
        : "r"((a)[0]), "r"((a)[1]), "r"((a)[2]), "r"((a)[3]), "r"(b0), "r"(b1))

#define MMA_F16(d, a, b0, b1) \
    asm volatile("mma.sync.aligned.m16n8k16.row.col.f32.f16.f16.f32 " \
        "{%0,%1,%2,%3}, {%4,%5,%6,%7}, {%8,%9}, {%0,%1,%2,%3};" \
        : "+f"((d)[0]), "+f"((d)[1]), "+f"((d)[2]), "+f"((d)[3]) \
        : "r"((a)[0]), "r"((a)[1]), "r"((a)[2]), "r"((a)[3]), "r"(b0), "r"(b1))

__device__ __forceinline__ uint32_t pack_hi(float x, float y) {
    __nv_bfloat162 v(__float2bfloat16(x), __float2bfloat16(y));
    return *(uint32_t*)&v;
}
__device__ __forceinline__ uint32_t pack_lo(float x, float y) {
    float hx = __bfloat162float(__float2bfloat16(x));
    float hy = __bfloat162float(__float2bfloat16(y));
    __nv_bfloat162 v(__float2bfloat16(x - hx), __float2bfloat16(y - hy));
    return *(uint32_t*)&v;
}
__device__ __forceinline__ uint32_t pack_hi16(float x, float y) {
    __half2 v = __floats2half2_rn(x, y);
    return *(uint32_t*)&v;
}
__device__ __forceinline__ uint32_t pack_lo16(float x, float y) {
    float hx = __half2float(__float2half_rn(x));
    float hy = __half2float(__float2half_rn(y));
    __half2 v = __floats2half2_rn(x - hx, y - hy);
    return *(uint32_t*)&v;
}

// ---------------------------------------------------------------------------
// fp32 -> bf16 hi/lo split
// ---------------------------------------------------------------------------
__global__ void __launch_bounds__(256) conv_split(const float* __restrict__ src,
                                                  __nv_bfloat16* __restrict__ hi,
                                                  __nv_bfloat16* __restrict__ lo,
                                                  int n4)
{
    int i = blockIdx.x * blockDim.x + threadIdx.x;
    if (i >= n4) return;
    float4 v = ((const float4*)src)[i];
    uint32_t* hp = (uint32_t*)hi;
    uint32_t* lp = (uint32_t*)lo;
    hp[2*i]   = pack_hi(v.x, v.y);
    hp[2*i+1] = pack_hi(v.z, v.w);
    lp[2*i]   = pack_lo(v.x, v.y);
    lp[2*i+1] = pack_lo(v.z, v.w);
}

// ---------------------------------------------------------------------------
// Projection GEMM (3-term split bf16), 128x128 tile, BK=64, double buffered.
// OUTMODE 0: fp32 row-major. OUTMODE 1: bf16 hi/lo head-split.
// OUTMODE 2: fp16 hi/lo head-split (for V).
// ---------------------------------------------------------------------------
template<int OUTMODE>
__global__ void __launch_bounds__(256,2) gemm_proj(
    const __nv_bfloat16* __restrict__ Ah, const __nv_bfloat16* __restrict__ Al,
    const __nv_bfloat16* __restrict__ Wh, const __nv_bfloat16* __restrict__ Wl,
    const float* __restrict__ bias,
    float* __restrict__ outF,
    __nv_bfloat16* __restrict__ outH, __nv_bfloat16* __restrict__ outL)
{
    __nv_bfloat16* sm = (__nv_bfloat16*)smraw;
    const int tid  = threadIdx.x;
    const int lane = tid & 31;
    const int wid  = tid >> 5;
    const int wm   = wid & 3;
    const int wn   = wid >> 2;
    const int row0 = blockIdx.y * 128;
    const int col0 = blockIdx.x * 128;
    const uint32_t sbase = smem_u32(sm);

    float acc[2][8][4];
    #pragma unroll
    for (int i = 0; i < 2; i++)
        #pragma unroll
        for (int j = 0; j < 8; j++)
            #pragma unroll
            for (int q = 0; q < 4; q++) acc[i][j][q] = 0.f;

    #define ISSUE(t) do {                                                      \
        const int p  = (t) >> 4;                                               \
        const int k0 = ((t) & 15) << 6;                                        \
        const __nv_bfloat16* Ap = (p == 1) ? Al : Ah;                          \
        const __nv_bfloat16* Wp = (p == 2) ? Wl : Wh;                          \
        const uint32_t sA = sbase + ((t & 1) * 9216) * 2;                      \
        const uint32_t sW = sbase + (18432 + (t & 1) * 9216) * 2;              \
        _Pragma("unroll")                                                      \
        for (int i_ = 0; i_ < 4; i_++) {                                       \
            int idx = tid + i_ * 256;                                          \
            int r = idx >> 3, ch = idx & 7;                                    \
            CP16(sA + (r * 72 + ch * 8) * 2,                                   \
                 Ap + (size_t)(row0 + r) * DD + k0 + ch * 8);                  \
            CP16(sW + (r * 72 + ch * 8) * 2,                                   \
                 Wp + (size_t)(col0 + r) * DD + k0 + ch * 8);                  \
        }                                                                      \
        CPC();                                                                 \
    } while (0)

    ISSUE(0);
    for (int t = 0; t < 48; t++) {
        if (t + 1 < 48) { ISSUE(t + 1); CPW(1); }
        else            { CPW(0); }
        __syncthreads();
        const uint32_t sA = sbase + ((t & 1) * 9216) * 2;
        const uint32_t sW = sbase + (18432 + (t & 1) * 9216) * 2;
        #pragma unroll
        for (int ks = 0; ks < 4; ks++) {
            uint32_t a[2][4], bq[4][4];
            #pragma unroll
            for (int i = 0; i < 2; i++)
                LDSM4(a[i], sA + ((wm*32 + i*16 + (lane & 15)) * 72
                                  + ks*16 + (lane >> 4) * 8) * 2);
            #pragma unroll
            for (int jj = 0; jj < 4; jj++)
                LDSM4(bq[jj], sW + ((wn*64 + jj*16 + (lane & 15)) * 72
                                    + ks*16 + (lane >> 4) * 8) * 2);
            #pragma unroll
            for (int i = 0; i < 2; i++)
                #pragma unroll
                for (int j = 0; j < 8; j++) {
                    const int jj = j >> 1;
                    uint32_t b0 = (j & 1) ? bq[jj][1] : bq[jj][0];
                    uint32_t b1 = (j & 1) ? bq[jj][3] : bq[jj][2];
                    MMA_BF16(acc[i][j], a[i], b0, b1);
                }
        }
        __syncthreads();
    }
    #undef ISSUE

    const int bb = row0 >> 11;
    #pragma unroll
    for (int i = 0; i < 2; i++) {
        const int r  = row0 + wm*32 + i*16 + (lane >> 2);
        const int n  = r & 2047;
        #pragma unroll
        for (int j = 0; j < 8; j++) {
            const int c = col0 + wn*64 + j*8 + (lane & 3)*2;
            const float b0v = __ldg(bias + c), b1v = __ldg(bias + c + 1);
            const float v00 = acc[i][j][0] + b0v, v01 = acc[i][j][1] + b1v;
            const float v10 = acc[i][j][2] + b0v, v11 = acc[i][j][3] + b1v;
            if (OUTMODE == 0) {
                *(float2*)(outF + (size_t)r * DD + c)       = make_float2(v00, v01);
                *(float2*)(outF + (size_t)(r + 8) * DD + c) = make_float2(v10, v11);
            } else {
                const int h = c >> 6, dk = c & 63;
                const size_t a0 = ((((size_t)bb*HH + h)*NN + n)      << 6) + dk;
                const size_t a1 = ((((size_t)bb*HH + h)*NN + (n+8))  << 6) + dk;
                if (OUTMODE == 1) {
                    *(uint32_t*)(outH + a0) = pack_hi(v00, v01);
                    *(uint32_t*)(outL + a0) = pack_lo(v00, v01);
                    *(uint32_t*)(outH + a1) = pack_hi(v10, v11);
                    *(uint32_t*)(outL + a1) = pack_lo(v10, v11);
                } else {
                    *(uint32_t*)(outH + a0) = pack_hi16(v00, v01);
                    *(uint32_t*)(outL + a0) = pack_lo16(v00, v01);
                    *(uint32_t*)(outH + a1) = pack_hi16(v10, v11);
                    *(uint32_t*)(outL + a1) = pack_lo16(v10, v11);
                }
            }
        }
    }
}

// ---------------------------------------------------------------------------
// Fused flash attention middle: per (z, n0-tile of 128):
//   loop m-tiles: S = QK^T (3-term bf16) -> P = exp(S/8) masked (fp16)
//   P -> gmem scratch (unnormalized) ; O += P x V (fp16, V hi+lo 2-term)
// end: rowsum -> g_rowsum, O/rowsum -> TH/TL bf16 (b,n,h,dk)
// smem layout (bytes): Qh 0, Ql 18432, K[2] 36864(+18432 lo), V[2] 110592,
//                      P(fp16,stride 136) 184320.  total 219136.
// ---------------------------------------------------------------------------
#define FQH 0
#define FQL 18432
#define FK(s) (36864 + (s)*36864)
#define FV(s) (110592 + (s)*36864)
#define FP    184320
#define FLASH_SMEM 219136

__global__ void __launch_bounds__(256,1) flash_mma(
    const int* __restrict__ mask,
    __half* __restrict__ P16,
    const __nv_bfloat16* __restrict__ QH, const __nv_bfloat16* __restrict__ QL,
    const __nv_bfloat16* __restrict__ KH, const __nv_bfloat16* __restrict__ KL,
    const __half* __restrict__ VH, const __half* __restrict__ VL,
    float* __restrict__ rowsum,
    __nv_bfloat16* __restrict__ WtH, __nv_bfloat16* __restrict__ WtL)
{
    char* sm = smraw;
    __shared__ float srow[128];
    const int tid  = threadIdx.x;
    const int lane = tid & 31;
    const int wid  = tid >> 5;
    const int wm   = wid & 3;
    const int wn   = wid >> 2;
    const int z    = blockIdx.y;
    const int b    = z >> 4;
    const int h    = z & 15;
    const int n0   = blockIdx.x * 128;
    const uint32_t sb = smem_u32(sm);
    __half* smP = (__half*)(sm + FP);

    if (tid < 128) srow[tid] = 0.f;

    // ---- load Q hi/lo tiles (persistent)
    {
        const __nv_bfloat16* qh = QH + ((size_t)z*NN + n0) * DKK;
        const __nv_bfloat16* ql = QL + ((size_t)z*NN + n0) * DKK;
        #pragma unroll
        for (int i = 0; i < 4; i++) {
            int idx = tid + i * 256;
            int r = idx >> 3, ch = idx & 7;
            uint32_t off = (uint32_t)(r * 72 + ch * 8) * 2;
            CP16(sb + FQH + off, qh + (size_t)r * DKK + ch * 8);
            CP16(sb + FQL + off, ql + (size_t)r * DKK + ch * 8);
        }
    }

    #define FISSUE_KV(t) do {                                                  \
        const int st_ = (t) & 1;                                               \
        const __nv_bfloat16* kh = KH + ((size_t)z*MM + (t)*128) * DKK;         \
        const __nv_bfloat16* kl = KL + ((size_t)z*MM + (t)*128) * DKK;         \
        const __half* vh = VH + ((size_t)z*MM + (t)*128) * DKK;                \
        const __half* vl = VL + ((size_t)z*MM + (t)*128) * DKK;                \
        _Pragma("unroll")                                                      \
        for (int i_ = 0; i_ < 4; i_++) {                                       \
            int idx = tid + i_ * 256;                                          \
            int r = idx >> 3, ch = idx & 7;                                    \
            uint32_t off = (uint32_t)(r * 72 + ch * 8) * 2;                    \
            size_t go = (size_t)r * DKK + ch * 8;                              \
            CP16(sb + FK(st_) + off,          kh + go);                        \
            CP16(sb + FK(st_) + 18432 + off,  kl + go);                        \
            CP16(sb + FV(st_) + off,          vh + go);                        \
            CP16(sb + FV(st_) + 18432 + off,  vl + go);                        \
        }                                                                      \
        CPC();                                                                 \
    } while (0)

    FISSUE_KV(0);   // commits Q loads too (same group)

    float accO[8][4];
    #pragma unroll
    for (int j = 0; j < 8; j++)
        #pragma unroll
        for (int q = 0; q < 4; q++) accO[j][q] = 0.f;
    float rsum[4] = {0.f, 0.f, 0.f, 0.f};

    const float scl = 0.125f;
    const size_t prow = (size_t)z * NN + n0;

    for (int mt = 0; mt < 16; mt++) {
        const int st = mt & 1;
        CPW(0);
        __syncthreads();

        // ---- QK^T, 3-term bf16 split
        float acc[2][8][4];
        #pragma unroll
        for (int i = 0; i < 2; i++)
            #pragma unroll
            for (int j = 0; j < 8; j++)
                #pragma unroll
                for (int q = 0; q < 4; q++) acc[i][j][q] = 0.f;

        #pragma unroll
        for (int p = 0; p < 3; p++) {
            const uint32_t sA = sb + ((p == 1) ? FQL : FQH);
            const uint32_t sB = sb + FK(st) + ((p == 2) ? 18432 : 0);
            #pragma unroll
            for (int ks = 0; ks < 4; ks++) {
                uint32_t a[2][4], bq[4][4];
                #pragma unroll
                for (int i = 0; i < 2; i++)
                    LDSM4(a[i], sA + ((wm*32 + i*16 + (lane & 15)) * 72
                                      + ks*16 + (lane >> 4) * 8) * 2);
                #pragma unroll
                for (int jj = 0; jj < 4; jj++)
                    LDSM4(bq[jj], sB + ((wn*64 + jj*16 + (lane & 15)) * 72
                                        + ks*16 + (lane >> 4) * 8) * 2);
                #pragma unroll
                for (int i = 0; i < 2; i++)
                    #pragma unroll
                    for (int j = 0; j < 8; j++) {
                        const int jj = j >> 1;
                        uint32_t b0 = (j & 1) ? bq[jj][1] : bq[jj][0];
                        uint32_t b1 = (j & 1) ? bq[jj][3] : bq[jj][2];
                        MMA_BF16(acc[i][j], a[i], b0, b1);
                    }
            }
        }

        if (mt < 15) FISSUE_KV(mt + 1);   // overlap next K/V load with exp+PV

        // ---- exp epilogue: P fp16 to smem, rowsum accumulate
        const int m0 = mt * 128;
        #pragma unroll
        for (int i = 0; i < 2; i++) {
            const int r0 = wm*32 + i*16 + (lane >> 2);
            const int r1 = r0 + 8;
            const int* mr0 = mask + ((size_t)b*NN + n0 + r0) * MM + m0;
            const int* mr1 = mask + ((size_t)b*NN + n0 + r1) * MM + m0;
            #pragma unroll
            for (int j = 0; j < 8; j++) {
                const int cl = wn*64 + j*8 + (lane & 3)*2;
                int2 k0 = *(const int2*)(mr0 + cl);
                int2 k1 = *(const int2*)(mr1 + cl);
                float e00 = (k0.x == 1) ? 0.f : __expf(acc[i][j][0] * scl);
                float e01 = (k0.y == 1) ? 0.f : __expf(acc[i][j][1] * scl);
                float e10 = (k1.x == 1) ? 0.f : __expf(acc[i][j][2] * scl);
                float e11 = (k1.y == 1) ? 0.f : __expf(acc[i][j][3] * scl);
                rsum[i*2+0] += e00 + e01;
                rsum[i*2+1] += e10 + e11;
                *(__half2*)(smP + r0*136 + cl) = __floats2half2_rn(e00, e01);
                *(__half2*)(smP + r1*136 + cl) = __floats2half2_rn(e10, e11);
            }
        }
        __syncthreads();

        // ---- P smem -> gmem scratch (coalesced)
        #pragma unroll
        for (int it = 0; it < 8; it++) {
            int idx = tid + it * 256;
            int r = idx >> 4, q = idx & 15;
            *(uint4*)(P16 + (prow + r) * MM + m0 + q*8) =
                *(const uint4*)(smP + r*136 + q*8);
        }

        // ---- O += P x V (fp16; V hi + lo)
        #pragma unroll
        for (int ks = 0; ks < 8; ks++) {
            uint32_t a[4];
            LDSM4(a, sb + FP + ((wid*16 + (lane & 15)) * 136
                                + ks*16 + (lane >> 4) * 8) * 2);
            #pragma unroll
            for (int ve = 0; ve < 2; ve++) {
                const uint32_t sV = sb + FV(st) + ve * 18432;
                uint32_t bq[4][4];
                #pragma unroll
                for (int jj = 0; jj < 4; jj++)
                    LDSM4T(bq[jj], sV + ((ks*16 + ((lane >> 3) & 1)*8 + (lane & 7)) * 72
                                         + jj*16 + (lane >> 4) * 8) * 2);
                #pragma unroll
                for (int j = 0; j < 8; j++) {
                    const int jj = j >> 1;
                    uint32_t b0 = (j & 1) ? bq[jj][2] : bq[jj][0];
                    uint32_t b1 = (j & 1) ? bq[jj][3] : bq[jj][1];
                    MMA_F16(accO[j], a, b0, b1);
                }
            }
        }
        // loop-top __syncthreads() protects P & V buffers
    }
    #undef FISSUE_KV

    // ---- rowsum reduce (quad shfl -> smem atomics -> gmem)
    #pragma unroll
    for (int k = 0; k < 4; k++) {
        rsum[k] += __shfl_xor_sync(0xffffffffu, rsum[k], 1);
        rsum[k] += __shfl_xor_sync(0xffffffffu, rsum[k], 2);
    }
    __syncthreads();
    if ((lane & 3) == 0) {
        #pragma unroll
        for (int k = 0; k < 4; k++) {
            const int rl = wm*32 + (k >> 1)*16 + (k & 1)*8 + (lane >> 2);
            atomicAdd(&srow[rl], rsum[k]);
        }
    }
    __syncthreads();
    if (tid < 128) rowsum[prow + tid] = srow[tid];

    // ---- normalize O, write wt (b,n,h,dk) bf16 hi/lo
    const int rl = wid*16 + (lane >> 2);
    const float inv0 = 1.0f / srow[rl];
    const float inv1 = 1.0f / srow[rl + 8];
    const int n = n0 + rl;
    #pragma unroll
    for (int j = 0; j < 8; j++) {
        const int dk = j*8 + (lane & 3)*2;
        const size_t a0 = ((((size_t)b*NN + n)     * HH + h) << 6) + dk;
        const size_t a1 = ((((size_t)b*NN + n + 8) * HH + h) << 6) + dk;
        const float v00 = accO[j][0]*inv0, v01 = accO[j][1]*inv0;
        const float v10 = accO[j][2]*inv1, v11 = accO[j][3]*inv1;
        *(uint32_t*)(WtH + a0) = pack_hi(v00, v01);
        *(uint32_t*)(WtL + a0) = pack_lo(v00, v01);
        *(uint32_t*)(WtH + a1) = pack_hi(v10, v11);
        *(uint32_t*)(WtL + a1) = pack_lo(v10, v11);
    }
}

// ---------------------------------------------------------------------------
// beta = P16 * (1/rowsum), fp32 out. One block per row.
// ---------------------------------------------------------------------------
__global__ void __launch_bounds__(256) norm_beta(const __half* __restrict__ P16,
                                                 const float* __restrict__ rowsum,
                                                 float* __restrict__ beta)
{
    const size_t row = blockIdx.x;
    const float inv = 1.0f / __ldg(rowsum + row);
    const __half* src = P16 + row * MM;
    float* dst = beta + row * MM;
    const int t = threadIdx.x;
    uint4 v = *(const uint4*)(src + t * 8);
    const __half2* h2 = (const __half2*)&v;
    float4 o0, o1;
    float2 f;
    f = __half22float2(h2[0]); o0.x = f.x*inv; o0.y = f.y*inv;
    f = __half22float2(h2[1]); o0.z = f.x*inv; o0.w = f.y*inv;
    f = __half22float2(h2[2]); o1.x = f.x*inv; o1.y = f.y*inv;
    f = __half22float2(h2[3]); o1.z = f.x*inv; o1.w = f.y*inv;
    *(float4*)(dst + t*8)     = o0;
    *(float4*)(dst + t*8 + 4) = o1;
}

// ============================================================================
extern "C" void kernel_launch(void* const* d_in, const int* in_sizes, int n_in,
                              void* d_out, int out_size)
{
    const float* X    = (const float*)d_in[0];
    const float* Y    = (const float*)d_in[1];
    const int*   mask = (const int*)  d_in[2];
    const float* Wq   = (const float*)d_in[3];
    const float* bq   = (const float*)d_in[4];
    const float* Wk   = (const float*)d_in[5];
    const float* bk   = (const float*)d_in[6];
    const float* Wv   = (const float*)d_in[7];
    const float* bv   = (const float*)d_in[8];
    const float* Wo   = (const float*)d_in[9];
    const float* bo   = (const float*)d_in[10];
    float* out = (float*)d_out;

    const size_t ATTN = (size_t)BB * NN * DD;
    const size_t BETA = (size_t)BB * HH * NN * MM;

    void *bfp_, *bsp_, *rsp_, *p16_;
    cudaGetSymbolAddress(&bfp_, g_bf);
    cudaGetSymbolAddress(&bsp_, g_beta_scratch);
    cudaGetSymbolAddress(&rsp_, g_rowsum);
    cudaGetSymbolAddress(&p16_, g_p16);
    __nv_bfloat16* bf = (__nv_bfloat16*)bfp_;
    __half* P16 = (__half*)p16_;
    float* rowsum = (float*)rsp_;

    __nv_bfloat16* XH = bf + 0*EL_X;  __nv_bfloat16* XL = bf + 1*EL_X;
    __nv_bfloat16* YH = bf + 2*EL_X;  __nv_bfloat16* YL = bf + 3*EL_X;
    __nv_bfloat16* QH = bf + 4*EL_X;  __nv_bfloat16* QL = bf + 5*EL_X;
    __nv_bfloat16* KH = bf + 6*EL_X;  __nv_bfloat16* KL = bf + 7*EL_X;
    __nv_bfloat16* VHb = bf + 8*EL_X; __nv_bfloat16* VLb = bf + 9*EL_X;
    __nv_bfloat16* TH = bf + 10*EL_X; __nv_bfloat16* TL = bf + 11*EL_X;
    __nv_bfloat16* W0 = bf + 12*EL_X;
    __nv_bfloat16* WqH = W0 + 0*EL_W; __nv_bfloat16* WqL = W0 + 1*EL_W;
    __nv_bfloat16* WkH = W0 + 2*EL_W; __nv_bfloat16* WkL = W0 + 3*EL_W;
    __nv_bfloat16* WvH = W0 + 4*EL_W; __nv_bfloat16* WvL = W0 + 5*EL_W;
    __nv_bfloat16* WoH = W0 + 6*EL_W; __nv_bfloat16* WoL = W0 + 7*EL_W;

    float* beta = ((size_t)out_size >= ATTN + BETA) ? (out + ATTN)
                                                    : (float*)bsp_;

    const int SMP = 73728;
    cudaFuncSetAttribute(gemm_proj<0>, cudaFuncAttributeMaxDynamicSharedMemorySize, SMP);
    cudaFuncSetAttribute(gemm_proj<1>, cudaFuncAttributeMaxDynamicSharedMemorySize, SMP);
    cudaFuncSetAttribute(gemm_proj<2>, cudaFuncAttributeMaxDynamicSharedMemorySize, SMP);
    cudaFuncSetAttribute(flash_mma,    cudaFuncAttributeMaxDynamicSharedMemorySize, FLASH_SMEM);

    const int n4x = (int)(EL_X / 4);
    const int n4w = (int)(EL_W / 4);
    conv_split<<<(n4x + 255)/256, 256>>>(X,  XH, XL, n4x);
    conv_split<<<(n4x + 255)/256, 256>>>(Y,  YH, YL, n4x);
    conv_split<<<(n4w + 255)/256, 256>>>(Wq, WqH, WqL, n4w);
    conv_split<<<(n4w + 255)/256, 256>>>(Wk, WkH, WkL, n4w);
    conv_split<<<(n4w + 255)/256, 256>>>(Wv, WvH, WvL, n4w);
    conv_split<<<(n4w + 255)/256, 256>>>(Wo, WoH, WoL, n4w);

    const dim3 pgrid(DD/128, RR/128);
    gemm_proj<1><<<pgrid, 256, SMP>>>(XH, XL, WqH, WqL, bq, nullptr, QH, QL);
    gemm_proj<1><<<pgrid, 256, SMP>>>(YH, YL, WkH, WkL, bk, nullptr, KH, KL);
    gemm_proj<2><<<pgrid, 256, SMP>>>(YH, YL, WvH, WvL, bv, nullptr, VHb, VLb);

    flash_mma<<<dim3(NN/128, BB*HH), 256, FLASH_SMEM>>>(
        mask, P16, QH, QL, KH, KL,
        (const __half*)VHb, (const __half*)VLb, rowsum, TH, TL);

    norm_beta<<<BB*HH*NN, 256>>>(P16, rowsum, beta);

    gemm_proj<0><<<pgrid, 256, SMP>>>(TH, TL, WoH, WoL, bo, out, nullptr, nullptr);
}

// round 7
// speedup vs baseline: 1.5469x; 1.2459x over previous
#include <cuda_runtime.h>
#include <cuda_bf16.h>
#include <cuda_fp16.h>
#include <stdint.h>

#define BB 4
#define NN 2048
#define MM 2048
#define DD 1024
#define HH 16
#define DKK 64
#define RR (BB*NN)

#define EL_X ((size_t)RR*DD)     // 8,388,608
#define EL_W ((size_t)DD*DD)     // 1,048,576

// fp16 arena: 0 XH,1 XL,2 YH,3 YL,4 QH,5 QL,6 KH,7 VH,8 VL,9 TH,10 TL (EL_X each)
// then 4 single-fp16 weights (EL_W each)
__device__ __half g_f16[11*EL_X + 4*EL_W];
__device__ __half g_p16[(size_t)BB*HH*NN*MM];          // unnormalized exp scratch
__device__ float g_rowsum[(size_t)BB*HH*NN];
__device__ float g_beta_scratch[(size_t)BB*HH*NN*MM];  // fallback only

extern __shared__ char smraw[];   // single TU-wide dynamic smem symbol

// ---------------------------------------------------------------------------
__device__ __forceinline__ uint32_t smem_u32(const void* p) {
    uint32_t a;
    asm("{ .reg .u64 t; cvta.to.shared.u64 t, %1; cvt.u32.u64 %0, t; }"
        : "=r"(a) : "l"(p));
    return a;
}

#define CP16(s, g) \
    asm volatile("cp.async.cg.shared.global [%0], [%1], 16;" :: "r"(s), "l"(g))
#define CPC() asm volatile("cp.async.commit_group;" ::: "memory")
#define CPW(n) asm volatile("cp.async.wait_group %0;" :: "n"(n) : "memory")

#define LDSM4(r, addr) \
    asm volatile("ldmatrix.sync.aligned.m8n8.x4.shared.b16 {%0,%1,%2,%3}, [%4];" \
        : "=r"((r)[0]), "=r"((r)[1]), "=r"((r)[2]), "=r"((r)[3]) : "r"(addr))
#define LDSM4T(r, addr) \
    asm volatile("ldmatrix.sync.aligned.m8n8.x4.trans.shared.b16 {%0,%1,%2,%3}, [%4];" \
        : "=r"((r)[0]), "=r"((r)[1]), "=r"((r)[2]), "=r"((r)[3]) : "r"(addr))

#define MMA_F16(d, a, b0, b1) \
    asm volatile("mma.sync.aligned.m16n8k16.row.col.f32.f16.f16.f32 " \
        "{%0,%1,%2,%3}, {%4,%5,%6,%7}, {%8,%9}, {%0,%1,%2,%3};" \
        : "+f"((d)[0]), "+f"((d)[1]), "+f"((d)[2]), "+f"((d)[3]) \
        : "r"((a)[0]), "r"((a)[1]), "r"((a)[2]), "r"((a)[3]), "r"(b0), "r"(b1))

__device__ __forceinline__ uint32_t pack_hi16(float x, float y) {
    __half2 v = __floats2half2_rn(x, y);
    return *(uint32_t*)&v;
}
__device__ __forceinline__ uint32_t pack_lo16(float x, float y) {
    float hx = __half2float(__float2half_rn(x));
    float hy = __half2float(__float2half_rn(y));
    __half2 v = __floats2half2_rn(x - hx, y - hy);
    return *(uint32_t*)&v;
}

// ---------------------------------------------------------------------------
// fp32 -> fp16 hi/lo split (activations)
// ---------------------------------------------------------------------------
__global__ void __launch_bounds__(256) conv_split16(const float* __restrict__ src,
                                                    __half* __restrict__ hi,
                                                    __half* __restrict__ lo,
                                                    int n4)
{
    int i = blockIdx.x * blockDim.x + threadIdx.x;
    if (i >= n4) return;
    float4 v = ((const float4*)src)[i];
    uint32_t* hp = (uint32_t*)hi;
    uint32_t* lp = (uint32_t*)lo;
    hp[2*i]   = pack_hi16(v.x, v.y);
    hp[2*i+1] = pack_hi16(v.z, v.w);
    lp[2*i]   = pack_lo16(v.x, v.y);
    lp[2*i+1] = pack_lo16(v.z, v.w);
}

// fp32 -> fp16 single (weights; entries ~ +-0.031, safely in fp16 range)
__global__ void __launch_bounds__(256) conv_w16(const float* __restrict__ src,
                                                __half* __restrict__ dst, int n4)
{
    int i = blockIdx.x * blockDim.x + threadIdx.x;
    if (i >= n4) return;
    float4 v = ((const float4*)src)[i];
    uint32_t* hp = (uint32_t*)dst;
    hp[2*i]   = pack_hi16(v.x, v.y);
    hp[2*i+1] = pack_hi16(v.z, v.w);
}

// ---------------------------------------------------------------------------
// Projection GEMM: C = A @ W^T + bias. A fp16 hi/lo (2 passes), W single fp16.
// 128x128 tile, BK=64, 32 k-tiles, cp.async double buffered.
// OUTMODE 0: fp32 row-major. OUTMODE 1: fp16 hi/lo head-split.
// OUTMODE 2: fp16 single head-split (K).
// smem: A[2] @ 0/9216, W[2] @ 18432/27648 halfs (stride 72). 73728 B.
// ---------------------------------------------------------------------------
template<int OUTMODE>
__global__ void __launch_bounds__(256,2) gemm_proj(
    const __half* __restrict__ Ah, const __half* __restrict__ Al,
    const __half* __restrict__ W,
    const float* __restrict__ bias,
    float* __restrict__ outF,
    __half* __restrict__ outH, __half* __restrict__ outL)
{
    __half* sm = (__half*)smraw;
    const int tid  = threadIdx.x;
    const int lane = tid & 31;
    const int wid  = tid >> 5;
    const int wm   = wid & 3;
    const int wn   = wid >> 2;
    const int row0 = blockIdx.y * 128;
    const int col0 = blockIdx.x * 128;
    const uint32_t sbase = smem_u32(sm);

    float acc[2][8][4];
    #pragma unroll
    for (int i = 0; i < 2; i++)
        #pragma unroll
        for (int j = 0; j < 8; j++)
            #pragma unroll
            for (int q = 0; q < 4; q++) acc[i][j][q] = 0.f;

    #define ISSUE(t) do {                                                      \
        const int p  = (t) >> 4;                                               \
        const int k0 = ((t) & 15) << 6;                                        \
        const __half* Ap = p ? Al : Ah;                                        \
        const uint32_t sA = sbase + ((t & 1) * 9216) * 2;                      \
        const uint32_t sW = sbase + (18432 + (t & 1) * 9216) * 2;              \
        _Pragma("unroll")                                                      \
        for (int i_ = 0; i_ < 4; i_++) {                                       \
            int idx = tid + i_ * 256;                                          \
            int r = idx >> 3, ch = idx & 7;                                    \
            CP16(sA + (r * 72 + ch * 8) * 2,                                   \
                 Ap + (size_t)(row0 + r) * DD + k0 + ch * 8);                  \
            CP16(sW + (r * 72 + ch * 8) * 2,                                   \
                 W + (size_t)(col0 + r) * DD + k0 + ch * 8);                   \
        }                                                                      \
        CPC();                                                                 \
    } while (0)

    ISSUE(0);
    for (int t = 0; t < 32; t++) {
        if (t + 1 < 32) { ISSUE(t + 1); CPW(1); }
        else            { CPW(0); }
        __syncthreads();
        const uint32_t sA = sbase + ((t & 1) * 9216) * 2;
        const uint32_t sW = sbase + (18432 + (t & 1) * 9216) * 2;
        #pragma unroll
        for (int ks = 0; ks < 4; ks++) {
            uint32_t a[2][4], bq[4][4];
            #pragma unroll
            for (int i = 0; i < 2; i++)
                LDSM4(a[i], sA + ((wm*32 + i*16 + (lane & 15)) * 72
                                  + ks*16 + (lane >> 4) * 8) * 2);
            #pragma unroll
            for (int jj = 0; jj < 4; jj++)
                LDSM4(bq[jj], sW + ((wn*64 + jj*16 + (lane & 15)) * 72
                                    + ks*16 + (lane >> 4) * 8) * 2);
            #pragma unroll
            for (int i = 0; i < 2; i++)
                #pragma unroll
                for (int j = 0; j < 8; j++) {
                    const int jj = j >> 1;
                    uint32_t b0 = (j & 1) ? bq[jj][1] : bq[jj][0];
                    uint32_t b1 = (j & 1) ? bq[jj][3] : bq[jj][2];
                    MMA_F16(acc[i][j], a[i], b0, b1);
                }
        }
        __syncthreads();
    }
    #undef ISSUE

    const int bb = row0 >> 11;
    #pragma unroll
    for (int i = 0; i < 2; i++) {
        const int r  = row0 + wm*32 + i*16 + (lane >> 2);
        const int n  = r & 2047;
        #pragma unroll
        for (int j = 0; j < 8; j++) {
            const int c = col0 + wn*64 + j*8 + (lane & 3)*2;
            const float b0v = __ldg(bias + c), b1v = __ldg(bias + c + 1);
            const float v00 = acc[i][j][0] + b0v, v01 = acc[i][j][1] + b1v;
            const float v10 = acc[i][j][2] + b0v, v11 = acc[i][j][3] + b1v;
            if (OUTMODE == 0) {
                *(float2*)(outF + (size_t)r * DD + c)       = make_float2(v00, v01);
                *(float2*)(outF + (size_t)(r + 8) * DD + c) = make_float2(v10, v11);
            } else {
                const int h = c >> 6, dk = c & 63;
                const size_t a0 = ((((size_t)bb*HH + h)*NN + n)      << 6) + dk;
                const size_t a1 = ((((size_t)bb*HH + h)*NN + (n+8))  << 6) + dk;
                *(uint32_t*)(outH + a0) = pack_hi16(v00, v01);
                *(uint32_t*)(outH + a1) = pack_hi16(v10, v11);
                if (OUTMODE == 1) {
                    *(uint32_t*)(outL + a0) = pack_lo16(v00, v01);
                    *(uint32_t*)(outL + a1) = pack_lo16(v10, v11);
                }
            }
        }
    }
}

// ---------------------------------------------------------------------------
// Fused flash middle: per (z, 128-row q-tile):
//   S = QK^T (Q hi/lo fp16 2 passes, K single fp16) -> P = exp(S/8) masked fp16
//   P -> gmem (unnormalized); O += P x V (V fp16 hi/lo, 2 passes)
// end: rowsum -> gmem, O/rowsum -> TH/TL fp16 hi/lo (b,n,h,dk)
// smem: Qh 0, Ql 18432, K[2] 36864, V[2] 73728 (hi +0 / lo +18432),
//       P 147456 (fp16 stride 136). total 182272 B.
// ---------------------------------------------------------------------------
#define FQH 0
#define FQL 18432
#define FK(s) (36864 + (s)*18432)
#define FV(s) (73728 + (s)*36864)
#define FP    147456
#define FLASH_SMEM 182272

__global__ void __launch_bounds__(256,1) flash_mma(
    const int* __restrict__ mask,
    __half* __restrict__ P16,
    const __half* __restrict__ QH, const __half* __restrict__ QL,
    const __half* __restrict__ KH,
    const __half* __restrict__ VH, const __half* __restrict__ VL,
    float* __restrict__ rowsum,
    __half* __restrict__ WtH, __half* __restrict__ WtL)
{
    char* sm = smraw;
    __shared__ float srow[128];
    const int tid  = threadIdx.x;
    const int lane = tid & 31;
    const int wid  = tid >> 5;
    const int wm   = wid & 3;
    const int wn   = wid >> 2;
    const int z    = blockIdx.y;
    const int b    = z >> 4;
    const int h    = z & 15;
    const int n0   = blockIdx.x * 128;
    const uint32_t sb = smem_u32(sm);
    __half* smP = (__half*)(sm + FP);

    if (tid < 128) srow[tid] = 0.f;

    // ---- load Q hi/lo tiles (persistent)
    {
        const __half* qh = QH + ((size_t)z*NN + n0) * DKK;
        const __half* ql = QL + ((size_t)z*NN + n0) * DKK;
        #pragma unroll
        for (int i = 0; i < 4; i++) {
            int idx = tid + i * 256;
            int r = idx >> 3, ch = idx & 7;
            uint32_t off = (uint32_t)(r * 72 + ch * 8) * 2;
            CP16(sb + FQH + off, qh + (size_t)r * DKK + ch * 8);
            CP16(sb + FQL + off, ql + (size_t)r * DKK + ch * 8);
        }
    }

    #define FISSUE_KV(t) do {                                                  \
        const int st_ = (t) & 1;                                               \
        const __half* kh = KH + ((size_t)z*MM + (t)*128) * DKK;                \
        const __half* vh = VH + ((size_t)z*MM + (t)*128) * DKK;                \
        const __half* vl = VL + ((size_t)z*MM + (t)*128) * DKK;                \
        _Pragma("unroll")                                                      \
        for (int i_ = 0; i_ < 4; i_++) {                                       \
            int idx = tid + i_ * 256;                                          \
            int r = idx >> 3, ch = idx & 7;                                    \
            uint32_t off = (uint32_t)(r * 72 + ch * 8) * 2;                    \
            size_t go = (size_t)r * DKK + ch * 8;                              \
            CP16(sb + FK(st_) + off,          kh + go);                        \
            CP16(sb + FV(st_) + off,          vh + go);                        \
            CP16(sb + FV(st_) + 18432 + off,  vl + go);                        \
        }                                                                      \
        CPC();                                                                 \
    } while (0)

    FISSUE_KV(0);   // commits Q loads too (same group)

    float accO[8][4];
    #pragma unroll
    for (int j = 0; j < 8; j++)
        #pragma unroll
        for (int q = 0; q < 4; q++) accO[j][q] = 0.f;
    float rsum[4] = {0.f, 0.f, 0.f, 0.f};

    const float scl = 0.125f;
    const size_t prow = (size_t)z * NN + n0;

    for (int mt = 0; mt < 16; mt++) {
        const int st = mt & 1;
        CPW(0);
        __syncthreads();

        // ---- QK^T: 2 passes (Qh*K + Ql*K)
        float acc[2][8][4];
        #pragma unroll
        for (int i = 0; i < 2; i++)
            #pragma unroll
            for (int j = 0; j < 8; j++)
                #pragma unroll
                for (int q = 0; q < 4; q++) acc[i][j][q] = 0.f;

        #pragma unroll
        for (int p = 0; p < 2; p++) {
            const uint32_t sA = sb + (p ? FQL : FQH);
            const uint32_t sB = sb + FK(st);
            #pragma unroll
            for (int ks = 0; ks < 4; ks++) {
                uint32_t a[2][4], bq[4][4];
                #pragma unroll
                for (int i = 0; i < 2; i++)
                    LDSM4(a[i], sA + ((wm*32 + i*16 + (lane & 15)) * 72
                                      + ks*16 + (lane >> 4) * 8) * 2);
                #pragma unroll
                for (int jj = 0; jj < 4; jj++)
                    LDSM4(bq[jj], sB + ((wn*64 + jj*16 + (lane & 15)) * 72
                                        + ks*16 + (lane >> 4) * 8) * 2);
                #pragma unroll
                for (int i = 0; i < 2; i++)
                    #pragma unroll
                    for (int j = 0; j < 8; j++) {
                        const int jj = j >> 1;
                        uint32_t b0 = (j & 1) ? bq[jj][1] : bq[jj][0];
                        uint32_t b1 = (j & 1) ? bq[jj][3] : bq[jj][2];
                        MMA_F16(acc[i][j], a[i], b0, b1);
                    }
            }
        }

        if (mt < 15) FISSUE_KV(mt + 1);   // overlap next K/V load with exp+PV

        // ---- exp epilogue: P fp16 to smem, rowsum accumulate
        const int m0 = mt * 128;
        #pragma unroll
        for (int i = 0; i < 2; i++) {
            const int r0 = wm*32 + i*16 + (lane >> 2);
            const int r1 = r0 + 8;
            const int* mr0 = mask + ((size_t)b*NN + n0 + r0) * MM + m0;
            const int* mr1 = mask + ((size_t)b*NN + n0 + r1) * MM + m0;
            #pragma unroll
            for (int j = 0; j < 8; j++) {
                const int cl = wn*64 + j*8 + (lane & 3)*2;
                int2 k0 = *(const int2*)(mr0 + cl);
                int2 k1 = *(const int2*)(mr1 + cl);
                float e00 = (k0.x == 1) ? 0.f : __expf(acc[i][j][0] * scl);
                float e01 = (k0.y == 1) ? 0.f : __expf(acc[i][j][1] * scl);
                float e10 = (k1.x == 1) ? 0.f : __expf(acc[i][j][2] * scl);
                float e11 = (k1.y == 1) ? 0.f : __expf(acc[i][j][3] * scl);
                rsum[i*2+0] += e00 + e01;
                rsum[i*2+1] += e10 + e11;
                *(__half2*)(smP + r0*136 + cl) = __floats2half2_rn(e00, e01);
                *(__half2*)(smP + r1*136 + cl) = __floats2half2_rn(e10, e11);
            }
        }
        __syncthreads();

        // ---- P smem -> gmem scratch (coalesced)
        #pragma unroll
        for (int it = 0; it < 8; it++) {
            int idx = tid + it * 256;
            int r = idx >> 4, q = idx & 15;
            *(uint4*)(P16 + (prow + r) * MM + m0 + q*8) =
                *(const uint4*)(smP + r*136 + q*8);
        }

        // ---- O += P x V (V hi + lo)
        #pragma unroll
        for (int ks = 0; ks < 8; ks++) {
            uint32_t a[4];
            LDSM4(a, sb + FP + ((wid*16 + (lane & 15)) * 136
                                + ks*16 + (lane >> 4) * 8) * 2);
            #pragma unroll
            for (int ve = 0; ve < 2; ve++) {
                const uint32_t sV = sb + FV(st) + ve * 18432;
                uint32_t bq[4][4];
                #pragma unroll
                for (int jj = 0; jj < 4; jj++)
                    LDSM4T(bq[jj], sV + ((ks*16 + ((lane >> 3) & 1)*8 + (lane & 7)) * 72
                                         + jj*16 + (lane >> 4) * 8) * 2);
                #pragma unroll
                for (int j = 0; j < 8; j++) {
                    const int jj = j >> 1;
                    uint32_t b0 = (j & 1) ? bq[jj][2] : bq[jj][0];
                    uint32_t b1 = (j & 1) ? bq[jj][3] : bq[jj][1];
                    MMA_F16(accO[j], a, b0, b1);
                }
            }
        }
        // loop-top __syncthreads() protects P & V buffers
    }
    #undef FISSUE_KV

    // ---- rowsum reduce
    #pragma unroll
    for (int k = 0; k < 4; k++) {
        rsum[k] += __shfl_xor_sync(0xffffffffu, rsum[k], 1);
        rsum[k] += __shfl_xor_sync(0xffffffffu, rsum[k], 2);
    }
    __syncthreads();
    if ((lane & 3) == 0) {
        #pragma unroll
        for (int k = 0; k < 4; k++) {
            const int rl = wm*32 + (k >> 1)*16 + (k & 1)*8 + (lane >> 2);
            atomicAdd(&srow[rl], rsum[k]);
        }
    }
    __syncthreads();
    if (tid < 128) rowsum[prow + tid] = srow[tid];

    // ---- normalize O, write wt (b,n,h,dk) fp16 hi/lo
    const int rl = wid*16 + (lane >> 2);
    const float inv0 = 1.0f / srow[rl];
    const float inv1 = 1.0f / srow[rl + 8];
    const int n = n0 + rl;
    #pragma unroll
    for (int j = 0; j < 8; j++) {
        const int dk = j*8 + (lane & 3)*2;
        const size_t a0 = ((((size_t)b*NN + n)     * HH + h) << 6) + dk;
        const size_t a1 = ((((size_t)b*NN + n + 8) * HH + h) << 6) + dk;
        const float v00 = accO[j][0]*inv0, v01 = accO[j][1]*inv0;
        const float v10 = accO[j][2]*inv1, v11 = accO[j][3]*inv1;
        *(uint32_t*)(WtH + a0) = pack_hi16(v00, v01);
        *(uint32_t*)(WtL + a0) = pack_lo16(v00, v01);
        *(uint32_t*)(WtH + a1) = pack_hi16(v10, v11);
        *(uint32_t*)(WtL + a1) = pack_lo16(v10, v11);
    }
}

// ---------------------------------------------------------------------------
// beta = P16 * (1/rowsum), fp32 out. One block per row.
// ---------------------------------------------------------------------------
__global__ void __launch_bounds__(256) norm_beta(const __half* __restrict__ P16,
                                                 const float* __restrict__ rowsum,
                                                 float* __restrict__ beta)
{
    const size_t row = blockIdx.x;
    const float inv = 1.0f / __ldg(rowsum + row);
    const __half* src = P16 + row * MM;
    float* dst = beta + row * MM;
    const int t = threadIdx.x;
    uint4 v = *(const uint4*)(src + t * 8);
    const __half2* h2 = (const __half2*)&v;
    float4 o0, o1;
    float2 f;
    f = __half22float2(h2[0]); o0.x = f.x*inv; o0.y = f.y*inv;
    f = __half22float2(h2[1]); o0.z = f.x*inv; o0.w = f.y*inv;
    f = __half22float2(h2[2]); o1.x = f.x*inv; o1.y = f.y*inv;
    f = __half22float2(h2[3]); o1.z = f.x*inv; o1.w = f.y*inv;
    *(float4*)(dst + t*8)     = o0;
    *(float4*)(dst + t*8 + 4) = o1;
}

// ============================================================================
extern "C" void kernel_launch(void* const* d_in, const int* in_sizes, int n_in,
                              void* d_out, int out_size)
{
    const float* X    = (const float*)d_in[0];
    const float* Y    = (const float*)d_in[1];
    const int*   mask = (const int*)  d_in[2];
    const float* Wq   = (const float*)d_in[3];
    const float* bq   = (const float*)d_in[4];
    const float* Wk   = (const float*)d_in[5];
    const float* bk   = (const float*)d_in[6];
    const float* Wv   = (const float*)d_in[7];
    const float* bv   = (const float*)d_in[8];
    const float* Wo   = (const float*)d_in[9];
    const float* bo   = (const float*)d_in[10];
    float* out = (float*)d_out;

    const size_t ATTN = (size_t)BB * NN * DD;
    const size_t BETA = (size_t)BB * HH * NN * MM;

    void *fp_, *bsp_, *rsp_, *p16_;
    cudaGetSymbolAddress(&fp_, g_f16);
    cudaGetSymbolAddress(&bsp_, g_beta_scratch);
    cudaGetSymbolAddress(&rsp_, g_rowsum);
    cudaGetSymbolAddress(&p16_, g_p16);
    __half* f16 = (__half*)fp_;
    __half* P16 = (__half*)p16_;
    float* rowsum = (float*)rsp_;

    __half* XH = f16 + 0*EL_X;  __half* XL = f16 + 1*EL_X;
    __half* YH = f16 + 2*EL_X;  __half* YL = f16 + 3*EL_X;
    __half* QH = f16 + 4*EL_X;  __half* QL = f16 + 5*EL_X;
    __half* KH = f16 + 6*EL_X;
    __half* VH = f16 + 7*EL_X;  __half* VL = f16 + 8*EL_X;
    __half* TH = f16 + 9*EL_X;  __half* TL = f16 + 10*EL_X;
    __half* W0 = f16 + 11*EL_X;
    __half* Wq16 = W0 + 0*EL_W;
    __half* Wk16 = W0 + 1*EL_W;
    __half* Wv16 = W0 + 2*EL_W;
    __half* Wo16 = W0 + 3*EL_W;

    float* beta = ((size_t)out_size >= ATTN + BETA) ? (out + ATTN)
                                                    : (float*)bsp_;

    const int SMP = 73728;
    cudaFuncSetAttribute(gemm_proj<0>, cudaFuncAttributeMaxDynamicSharedMemorySize, SMP);
    cudaFuncSetAttribute(gemm_proj<1>, cudaFuncAttributeMaxDynamicSharedMemorySize, SMP);
    cudaFuncSetAttribute(gemm_proj<2>, cudaFuncAttributeMaxDynamicSharedMemorySize, SMP);
    cudaFuncSetAttribute(flash_mma,    cudaFuncAttributeMaxDynamicSharedMemorySize, FLASH_SMEM);

    const int n4x = (int)(EL_X / 4);
    const int n4w = (int)(EL_W / 4);
    conv_split16<<<(n4x + 255)/256, 256>>>(X,  XH, XL, n4x);
    conv_split16<<<(n4x + 255)/256, 256>>>(Y,  YH, YL, n4x);
    conv_w16<<<(n4w + 255)/256, 256>>>(Wq, Wq16, n4w);
    conv_w16<<<(n4w + 255)/256, 256>>>(Wk, Wk16, n4w);
    conv_w16<<<(n4w + 255)/256, 256>>>(Wv, Wv16, n4w);
    conv_w16<<<(n4w + 255)/256, 256>>>(Wo, Wo16, n4w);

    const dim3 pgrid(DD/128, RR/128);
    gemm_proj<1><<<pgrid, 256, SMP>>>(XH, XL, Wq16, bq, nullptr, QH, QL);
    gemm_proj<2><<<pgrid, 256, SMP>>>(YH, YL, Wk16, bk, nullptr, KH, nullptr);
    gemm_proj<1><<<pgrid, 256, SMP>>>(YH, YL, Wv16, bv, nullptr, VH, VL);

    flash_mma<<<dim3(NN/128, BB*HH), 256, FLASH_SMEM>>>(
        mask, P16, QH, QL, KH, VH, VL, rowsum, TH, TL);

    norm_beta<<<BB*HH*NN, 256>>>(P16, rowsum, beta);

    gemm_proj<0><<<pgrid, 256, SMP>>>(TH, TL, Wo16, bo, out, nullptr, nullptr);
}

// round 8
// speedup vs baseline: 2.1483x; 1.3888x over previous
#include <cuda_runtime.h>
#include <cuda_fp16.h>
#include <stdint.h>

#define BB 4
#define NN 2048
#define MM 2048
#define DD 1024
#define HH 16
#define DKK 64
#define RR (BB*NN)

#define EL_X ((size_t)RR*DD)     // 8,388,608
#define EL_W ((size_t)DD*DD)     // 1,048,576

// fp16 arena: 0 X, 1 Y, 2 Q, 3 K, 4 V, 5 T (EL_X each), then 4 weights (EL_W)
__device__ __half g_f16[6*EL_X + 4*EL_W];
__device__ __half g_p16[(size_t)BB*HH*NN*MM];          // unnormalized exp scratch
__device__ float g_rowsum[(size_t)BB*HH*NN];
__device__ float g_beta_scratch[(size_t)BB*HH*NN*MM];  // fallback only

extern __shared__ char smraw[];

// ---------------------------------------------------------------------------
__device__ __forceinline__ uint32_t smem_u32(const void* p) {
    uint32_t a;
    asm("{ .reg .u64 t; cvta.to.shared.u64 t, %1; cvt.u32.u64 %0, t; }"
        : "=r"(a) : "l"(p));
    return a;
}

#define CP16(s, g) \
    asm volatile("cp.async.cg.shared.global [%0], [%1], 16;" :: "r"(s), "l"(g))
#define CPC() asm volatile("cp.async.commit_group;" ::: "memory")
#define CPW(n) asm volatile("cp.async.wait_group %0;" :: "n"(n) : "memory")

#define LDSM4(r, addr) \
    asm volatile("ldmatrix.sync.aligned.m8n8.x4.shared.b16 {%0,%1,%2,%3}, [%4];" \
        : "=r"((r)[0]), "=r"((r)[1]), "=r"((r)[2]), "=r"((r)[3]) : "r"(addr))
#define LDSM4T(r, addr) \
    asm volatile("ldmatrix.sync.aligned.m8n8.x4.trans.shared.b16 {%0,%1,%2,%3}, [%4];" \
        : "=r"((r)[0]), "=r"((r)[1]), "=r"((r)[2]), "=r"((r)[3]) : "r"(addr))

#define MMA_F16(d, a, b0, b1) \
    asm volatile("mma.sync.aligned.m16n8k16.row.col.f32.f16.f16.f32 " \
        "{%0,%1,%2,%3}, {%4,%5,%6,%7}, {%8,%9}, {%0,%1,%2,%3};" \
        : "+f"((d)[0]), "+f"((d)[1]), "+f"((d)[2]), "+f"((d)[3]) \
        : "r"((a)[0]), "r"((a)[1]), "r"((a)[2]), "r"((a)[3]), "r"(b0), "r"(b1))

__device__ __forceinline__ uint32_t pack16(float x, float y) {
    __half2 v = __floats2half2_rn(x, y);
    return *(uint32_t*)&v;
}

// ---------------------------------------------------------------------------
// fp32 -> fp16 single conversion
// ---------------------------------------------------------------------------
__global__ void __launch_bounds__(256) conv_f16(const float* __restrict__ src,
                                                __half* __restrict__ dst, int n4)
{
    int i = blockIdx.x * blockDim.x + threadIdx.x;
    if (i >= n4) return;
    float4 v = ((const float4*)src)[i];
    uint32_t* hp = (uint32_t*)dst;
    hp[2*i]   = pack16(v.x, v.y);
    hp[2*i+1] = pack16(v.z, v.w);
}

// ---------------------------------------------------------------------------
// Projection GEMM: C = A @ W^T + bias, single fp16 both operands, 1 pass.
// 128x128 tile, BK=64, 16 k-tiles, cp.async double buffered.
// OUTMODE 0: fp32 row-major. OUTMODE 1: fp16 head-split (b,h,seq,dk).
// smem: A[2] @ 0/9216, W[2] @ 18432/27648 halfs (stride 72). 73728 B.
// ---------------------------------------------------------------------------
template<int OUTMODE>
__global__ void __launch_bounds__(256,2) gemm_proj(
    const __half* __restrict__ A,
    const __half* __restrict__ W,
    const float* __restrict__ bias,
    float* __restrict__ outF,
    __half* __restrict__ outH)
{
    __half* sm = (__half*)smraw;
    const int tid  = threadIdx.x;
    const int lane = tid & 31;
    const int wid  = tid >> 5;
    const int wm   = wid & 3;
    const int wn   = wid >> 2;
    const int row0 = blockIdx.y * 128;
    const int col0 = blockIdx.x * 128;
    const uint32_t sbase = smem_u32(sm);

    float acc[2][8][4];
    #pragma unroll
    for (int i = 0; i < 2; i++)
        #pragma unroll
        for (int j = 0; j < 8; j++)
            #pragma unroll
            for (int q = 0; q < 4; q++) acc[i][j][q] = 0.f;

    #define ISSUE(t) do {                                                      \
        const int k0 = (t) << 6;                                               \
        const uint32_t sA = sbase + (((t) & 1) * 9216) * 2;                    \
        const uint32_t sW = sbase + (18432 + ((t) & 1) * 9216) * 2;            \
        _Pragma("unroll")                                                      \
        for (int i_ = 0; i_ < 4; i_++) {                                       \
            int idx = tid + i_ * 256;                                          \
            int r = idx >> 3, ch = idx & 7;                                    \
            CP16(sA + (r * 72 + ch * 8) * 2,                                   \
                 A + (size_t)(row0 + r) * DD + k0 + ch * 8);                   \
            CP16(sW + (r * 72 + ch * 8) * 2,                                   \
                 W + (size_t)(col0 + r) * DD + k0 + ch * 8);                   \
        }                                                                      \
        CPC();                                                                 \
    } while (0)

    ISSUE(0);
    for (int t = 0; t < 16; t++) {
        if (t + 1 < 16) { ISSUE(t + 1); CPW(1); }
        else            { CPW(0); }
        __syncthreads();
        const uint32_t sA = sbase + ((t & 1) * 9216) * 2;
        const uint32_t sW = sbase + (18432 + (t & 1) * 9216) * 2;
        #pragma unroll
        for (int ks = 0; ks < 4; ks++) {
            uint32_t a[2][4], bq[4][4];
            #pragma unroll
            for (int i = 0; i < 2; i++)
                LDSM4(a[i], sA + ((wm*32 + i*16 + (lane & 15)) * 72
                                  + ks*16 + (lane >> 4) * 8) * 2);
            #pragma unroll
            for (int jj = 0; jj < 4; jj++)
                LDSM4(bq[jj], sW + ((wn*64 + jj*16 + (lane & 15)) * 72
                                    + ks*16 + (lane >> 4) * 8) * 2);
            #pragma unroll
            for (int i = 0; i < 2; i++)
                #pragma unroll
                for (int j = 0; j < 8; j++) {
                    const int jj = j >> 1;
                    uint32_t b0 = (j & 1) ? bq[jj][1] : bq[jj][0];
                    uint32_t b1 = (j & 1) ? bq[jj][3] : bq[jj][2];
                    MMA_F16(acc[i][j], a[i], b0, b1);
                }
        }
        __syncthreads();
    }
    #undef ISSUE

    const int bb = row0 >> 11;
    #pragma unroll
    for (int i = 0; i < 2; i++) {
        const int r  = row0 + wm*32 + i*16 + (lane >> 2);
        const int n  = r & 2047;
        #pragma unroll
        for (int j = 0; j < 8; j++) {
            const int c = col0 + wn*64 + j*8 + (lane & 3)*2;
            const float b0v = __ldg(bias + c), b1v = __ldg(bias + c + 1);
            const float v00 = acc[i][j][0] + b0v, v01 = acc[i][j][1] + b1v;
            const float v10 = acc[i][j][2] + b0v, v11 = acc[i][j][3] + b1v;
            if (OUTMODE == 0) {
                *(float2*)(outF + (size_t)r * DD + c)       = make_float2(v00, v01);
                *(float2*)(outF + (size_t)(r + 8) * DD + c) = make_float2(v10, v11);
            } else {
                const int h = c >> 6, dk = c & 63;
                const size_t a0 = ((((size_t)bb*HH + h)*NN + n)      << 6) + dk;
                const size_t a1 = ((((size_t)bb*HH + h)*NN + (n+8))  << 6) + dk;
                *(uint32_t*)(outH + a0) = pack16(v00, v01);
                *(uint32_t*)(outH + a1) = pack16(v10, v11);
            }
        }
    }
}

// ---------------------------------------------------------------------------
// Fused flash middle: per (z, 128-row q-tile):
//   S = QK^T (single fp16, 1 pass) -> P = exp(S/8) masked, fp16
//   P -> gmem (unnormalized); O += P x V (single fp16, 1 pass)
// end: rowsum -> gmem, O/rowsum -> T fp16 (b,n,h,dk)
// smem: Q 0 (18432), K[2] 18432/36864, V[2] 55296/73728, P 92160 (stride 136).
// total 126976 B.
// ---------------------------------------------------------------------------
#define FQ  0
#define FK(s) (18432 + (s)*18432)
#define FV(s) (55296 + (s)*18432)
#define FP    92160
#define FLASH_SMEM 126976

__global__ void __launch_bounds__(256,1) flash_mma(
    const int* __restrict__ mask,
    __half* __restrict__ P16,
    const __half* __restrict__ Q,
    const __half* __restrict__ K,
    const __half* __restrict__ V,
    float* __restrict__ rowsum,
    __half* __restrict__ Wt)
{
    char* sm = smraw;
    __shared__ float srow[128];
    const int tid  = threadIdx.x;
    const int lane = tid & 31;
    const int wid  = tid >> 5;
    const int wm   = wid & 3;
    const int wn   = wid >> 2;
    const int z    = blockIdx.y;
    const int b    = z >> 4;
    const int h    = z & 15;
    const int n0   = blockIdx.x * 128;
    const uint32_t sb = smem_u32(sm);
    __half* smP = (__half*)(sm + FP);

    if (tid < 128) srow[tid] = 0.f;

    // ---- load Q tile (persistent)
    {
        const __half* q = Q + ((size_t)z*NN + n0) * DKK;
        #pragma unroll
        for (int i = 0; i < 4; i++) {
            int idx = tid + i * 256;
            int r = idx >> 3, ch = idx & 7;
            CP16(sb + FQ + (uint32_t)(r * 72 + ch * 8) * 2,
                 q + (size_t)r * DKK + ch * 8);
        }
    }

    #define FISSUE_KV(t) do {                                                  \
        const int st_ = (t) & 1;                                               \
        const __half* kp = K + ((size_t)z*MM + (t)*128) * DKK;                 \
        const __half* vp = V + ((size_t)z*MM + (t)*128) * DKK;                 \
        _Pragma("unroll")                                                      \
        for (int i_ = 0; i_ < 4; i_++) {                                       \
            int idx = tid + i_ * 256;                                          \
            int r = idx >> 3, ch = idx & 7;                                    \
            uint32_t off = (uint32_t)(r * 72 + ch * 8) * 2;                    \
            size_t go = (size_t)r * DKK + ch * 8;                              \
            CP16(sb + FK(st_) + off, kp + go);                                 \
            CP16(sb + FV(st_) + off, vp + go);                                 \
        }                                                                      \
        CPC();                                                                 \
    } while (0)

    FISSUE_KV(0);   // commits Q loads too (same group)

    float accO[8][4];
    #pragma unroll
    for (int j = 0; j < 8; j++)
        #pragma unroll
        for (int q = 0; q < 4; q++) accO[j][q] = 0.f;
    float rsum[4] = {0.f, 0.f, 0.f, 0.f};

    const float scl = 0.125f;
    const size_t prow = (size_t)z * NN + n0;

    for (int mt = 0; mt < 16; mt++) {
        const int st = mt & 1;
        CPW(0);
        __syncthreads();

        // ---- QK^T (single pass)
        float acc[2][8][4];
        #pragma unroll
        for (int i = 0; i < 2; i++)
            #pragma unroll
            for (int j = 0; j < 8; j++)
                #pragma unroll
                for (int q = 0; q < 4; q++) acc[i][j][q] = 0.f;

        #pragma unroll
        for (int ks = 0; ks < 4; ks++) {
            uint32_t a[2][4], bq[4][4];
            #pragma unroll
            for (int i = 0; i < 2; i++)
                LDSM4(a[i], sb + FQ + ((wm*32 + i*16 + (lane & 15)) * 72
                                       + ks*16 + (lane >> 4) * 8) * 2);
            #pragma unroll
            for (int jj = 0; jj < 4; jj++)
                LDSM4(bq[jj], sb + FK(st) + ((wn*64 + jj*16 + (lane & 15)) * 72
                                             + ks*16 + (lane >> 4) * 8) * 2);
            #pragma unroll
            for (int i = 0; i < 2; i++)
                #pragma unroll
                for (int j = 0; j < 8; j++) {
                    const int jj = j >> 1;
                    uint32_t b0 = (j & 1) ? bq[jj][1] : bq[jj][0];
                    uint32_t b1 = (j & 1) ? bq[jj][3] : bq[jj][2];
                    MMA_F16(acc[i][j], a[i], b0, b1);
                }
        }

        if (mt < 15) FISSUE_KV(mt + 1);   // overlap next K/V load with exp+PV

        // ---- exp epilogue: P fp16 to smem, rowsum accumulate
        const int m0 = mt * 128;
        #pragma unroll
        for (int i = 0; i < 2; i++) {
            const int r0 = wm*32 + i*16 + (lane >> 2);
            const int r1 = r0 + 8;
            const int* mr0 = mask + ((size_t)b*NN + n0 + r0) * MM + m0;
            const int* mr1 = mask + ((size_t)b*NN + n0 + r1) * MM + m0;
            #pragma unroll
            for (int j = 0; j < 8; j++) {
                const int cl = wn*64 + j*8 + (lane & 3)*2;
                int2 k0 = *(const int2*)(mr0 + cl);
                int2 k1 = *(const int2*)(mr1 + cl);
                float e00 = (k0.x == 1) ? 0.f : __expf(acc[i][j][0] * scl);
                float e01 = (k0.y == 1) ? 0.f : __expf(acc[i][j][1] * scl);
                float e10 = (k1.x == 1) ? 0.f : __expf(acc[i][j][2] * scl);
                float e11 = (k1.y == 1) ? 0.f : __expf(acc[i][j][3] * scl);
                rsum[i*2+0] += e00 + e01;
                rsum[i*2+1] += e10 + e11;
                *(__half2*)(smP + r0*136 + cl) = __floats2half2_rn(e00, e01);
                *(__half2*)(smP + r1*136 + cl) = __floats2half2_rn(e10, e11);
            }
        }
        __syncthreads();

        // ---- P smem -> gmem scratch (coalesced)
        #pragma unroll
        for (int it = 0; it < 8; it++) {
            int idx = tid + it * 256;
            int r = idx >> 4, q = idx & 15;
            *(uint4*)(P16 + (prow + r) * MM + m0 + q*8) =
                *(const uint4*)(smP + r*136 + q*8);
        }

        // ---- O += P x V (single pass)
        #pragma unroll
        for (int ks = 0; ks < 8; ks++) {
            uint32_t a[4], bq[4][4];
            LDSM4(a, sb + FP + ((wid*16 + (lane & 15)) * 136
                                + ks*16 + (lane >> 4) * 8) * 2);
            #pragma unroll
            for (int jj = 0; jj < 4; jj++)
                LDSM4T(bq[jj], sb + FV(st) + ((ks*16 + ((lane >> 3) & 1)*8 + (lane & 7)) * 72
                                              + jj*16 + (lane >> 4) * 8) * 2);
            #pragma unroll
            for (int j = 0; j < 8; j++) {
                const int jj = j >> 1;
                uint32_t b0 = (j & 1) ? bq[jj][2] : bq[jj][0];
                uint32_t b1 = (j & 1) ? bq[jj][3] : bq[jj][1];
                MMA_F16(accO[j], a, b0, b1);
            }
        }
        // loop-top __syncthreads() protects P & V buffers
    }
    #undef FISSUE_KV

    // ---- rowsum reduce
    #pragma unroll
    for (int k = 0; k < 4; k++) {
        rsum[k] += __shfl_xor_sync(0xffffffffu, rsum[k], 1);
        rsum[k] += __shfl_xor_sync(0xffffffffu, rsum[k], 2);
    }
    __syncthreads();
    if ((lane & 3) == 0) {
        #pragma unroll
        for (int k = 0; k < 4; k++) {
            const int rl = wm*32 + (k >> 1)*16 + (k & 1)*8 + (lane >> 2);
            atomicAdd(&srow[rl], rsum[k]);
        }
    }
    __syncthreads();
    if (tid < 128) rowsum[prow + tid] = srow[tid];

    // ---- normalize O, write wt (b,n,h,dk) fp16
    const int rl = wid*16 + (lane >> 2);
    const float inv0 = 1.0f / srow[rl];
    const float inv1 = 1.0f / srow[rl + 8];
    const int n = n0 + rl;
    #pragma unroll
    for (int j = 0; j < 8; j++) {
        const int dk = j*8 + (lane & 3)*2;
        const size_t a0 = ((((size_t)b*NN + n)     * HH + h) << 6) + dk;
        const size_t a1 = ((((size_t)b*NN + n + 8) * HH + h) << 6) + dk;
        *(uint32_t*)(Wt + a0) = pack16(accO[j][0]*inv0, accO[j][1]*inv0);
        *(uint32_t*)(Wt + a1) = pack16(accO[j][2]*inv1, accO[j][3]*inv1);
    }
}

// ---------------------------------------------------------------------------
// beta = P16 * (1/rowsum), fp32 out. One block per row.
// ---------------------------------------------------------------------------
__global__ void __launch_bounds__(256) norm_beta(const __half* __restrict__ P16,
                                                 const float* __restrict__ rowsum,
                                                 float* __restrict__ beta)
{
    const size_t row = blockIdx.x;
    const float inv = 1.0f / __ldg(rowsum + row);
    const __half* src = P16 + row * MM;
    float* dst = beta + row * MM;
    const int t = threadIdx.x;
    uint4 v = *(const uint4*)(src + t * 8);
    const __half2* h2 = (const __half2*)&v;
    float4 o0, o1;
    float2 f;
    f = __half22float2(h2[0]); o0.x = f.x*inv; o0.y = f.y*inv;
    f = __half22float2(h2[1]); o0.z = f.x*inv; o0.w = f.y*inv;
    f = __half22float2(h2[2]); o1.x = f.x*inv; o1.y = f.y*inv;
    f = __half22float2(h2[3]); o1.z = f.x*inv; o1.w = f.y*inv;
    *(float4*)(dst + t*8)     = o0;
    *(float4*)(dst + t*8 + 4) = o1;
}

// ============================================================================
extern "C" void kernel_launch(void* const* d_in, const int* in_sizes, int n_in,
                              void* d_out, int out_size)
{
    const float* X    = (const float*)d_in[0];
    const float* Y    = (const float*)d_in[1];
    const int*   mask = (const int*)  d_in[2];
    const float* Wq   = (const float*)d_in[3];
    const float* bq   = (const float*)d_in[4];
    const float* Wk   = (const float*)d_in[5];
    const float* bk   = (const float*)d_in[6];
    const float* Wv   = (const float*)d_in[7];
    const float* bv   = (const float*)d_in[8];
    const float* Wo   = (const float*)d_in[9];
    const float* bo   = (const float*)d_in[10];
    float* out = (float*)d_out;

    const size_t ATTN = (size_t)BB * NN * DD;
    const size_t BETA = (size_t)BB * HH * NN * MM;

    void *fp_, *bsp_, *rsp_, *p16_;
    cudaGetSymbolAddress(&fp_, g_f16);
    cudaGetSymbolAddress(&bsp_, g_beta_scratch);
    cudaGetSymbolAddress(&rsp_, g_rowsum);
    cudaGetSymbolAddress(&p16_, g_p16);
    __half* f16 = (__half*)fp_;
    __half* P16 = (__half*)p16_;
    float* rowsum = (float*)rsp_;

    __half* X16 = f16 + 0*EL_X;
    __half* Y16 = f16 + 1*EL_X;
    __half* Q16 = f16 + 2*EL_X;
    __half* K16 = f16 + 3*EL_X;
    __half* V16 = f16 + 4*EL_X;
    __half* T16 = f16 + 5*EL_X;
    __half* W0  = f16 + 6*EL_X;
    __half* Wq16 = W0 + 0*EL_W;
    __half* Wk16 = W0 + 1*EL_W;
    __half* Wv16 = W0 + 2*EL_W;
    __half* Wo16 = W0 + 3*EL_W;

    float* beta = ((size_t)out_size >= ATTN + BETA) ? (out + ATTN)
                                                    : (float*)bsp_;

    const int SMP = 73728;
    cudaFuncSetAttribute(gemm_proj<0>, cudaFuncAttributeMaxDynamicSharedMemorySize, SMP);
    cudaFuncSetAttribute(gemm_proj<1>, cudaFuncAttributeMaxDynamicSharedMemorySize, SMP);
    cudaFuncSetAttribute(flash_mma,    cudaFuncAttributeMaxDynamicSharedMemorySize, FLASH_SMEM);

    const int n4x = (int)(EL_X / 4);
    const int n4w = (int)(EL_W / 4);
    conv_f16<<<(n4x + 255)/256, 256>>>(X,  X16, n4x);
    conv_f16<<<(n4x + 255)/256, 256>>>(Y,  Y16, n4x);
    conv_f16<<<(n4w + 255)/256, 256>>>(Wq, Wq16, n4w);
    conv_f16<<<(n4w + 255)/256, 256>>>(Wk, Wk16, n4w);
    conv_f16<<<(n4w + 255)/256, 256>>>(Wv, Wv16, n4w);
    conv_f16<<<(n4w + 255)/256, 256>>>(Wo, Wo16, n4w);

    const dim3 pgrid(DD/128, RR/128);
    gemm_proj<1><<<pgrid, 256, SMP>>>(X16, Wq16, bq, nullptr, Q16);
    gemm_proj<1><<<pgrid, 256, SMP>>>(Y16, Wk16, bk, nullptr, K16);
    gemm_proj<1><<<pgrid, 256, SMP>>>(Y16, Wv16, bv, nullptr, V16);

    flash_mma<<<dim3(NN/128, BB*HH), 256, FLASH_SMEM>>>(
        mask, P16, Q16, K16, V16, rowsum, T16);

    norm_beta<<<BB*HH*NN, 256>>>(P16, rowsum, beta);

    gemm_proj<0><<<pgrid, 256, SMP>>>(T16, Wo16, bo, out, nullptr);
}